// round 1
// baseline (speedup 1.0000x reference)
#include <cuda_runtime.h>
#include <math.h>

// Problem constants
#define NB 8
#define NL 2048
#define ND 512
#define BLD (NB*NL*ND)      // 8,388,608 elems per tensor
#define BLL_ ((long long)NB*NL*NL)  // 33,554,432 per direction score matrix

// Scratch (device globals: allocation-free per harness rules)
__device__ float g_q[2ULL*BLD];   // Q per direction; reused as context output after PV
__device__ float g_k[2ULL*BLD];
__device__ float g_v[2ULL*BLD];
__device__ float g_g[2ULL*BLD];   // gate pre-activations
__device__ float g_s[2ULL*BLL_];  // scores / probs

// ---------------------------------------------------------------------------
// Generic tiled FP32 GEMM.
//   BT = true : C[m,n] = alpha * sum_k A[m,k] * B[n,k]  (+bias[n])   "NT"
//   BT = false: C[m,n] = alpha * sum_k A[m,k] * B[k,n]  (+bias[n])   "NN"
// Tiles: 128x128x8, 256 threads, 8x8 per-thread microtile.
// Requires M%128==0, N%128==0, K%8==0 (all shapes here satisfy this).
// Batched via blockIdx.z with element strides sA/sB/sC.
// ---------------------------------------------------------------------------
template<bool BT>
__global__ __launch_bounds__(256, 2)
void gemm_k(const float* __restrict__ A, const float* __restrict__ Bm,
            const float* __restrict__ bias, float* __restrict__ C,
            int M, int N, int K, float alpha,
            long long sA, long long sB, long long sC)
{
    constexpr int BM = 128, BN = 128, BK = 8;
    __shared__ float As[BK][BM];
    __shared__ float Bs[BK][BN];

    A  += (long long)blockIdx.z * sA;
    Bm += (long long)blockIdx.z * sB;
    C  += (long long)blockIdx.z * sC;

    const int tid = threadIdx.x;
    const int tx = tid & 15;        // 0..15 -> N microtiles
    const int ty = tid >> 4;        // 0..15 -> M microtiles
    const int rowBase = blockIdx.y * BM;
    const int colBase = blockIdx.x * BN;

    // A global-load mapping: 128 rows x 8 k, float4 per thread (2 threads/row)
    const int aRow = tid >> 1;
    const int aK   = (tid & 1) * 4;
    const float* Ap = A + (long long)(rowBase + aRow) * K + aK;

    // B global-load mapping
    int bR, bK_;
    const float* Bp;
    if (BT) {  // B is (N,K) row-major: same pattern as A over N rows
        bR  = tid >> 1;
        bK_ = (tid & 1) * 4;
        Bp  = Bm + (long long)(colBase + bR) * K + bK_;
    } else {   // B is (K,N) row-major: 8 k-rows x 32 threads x float4
        bK_ = tid >> 5;           // 0..7
        bR  = (tid & 31) * 4;     // 0..124
        Bp  = Bm + (long long)bK_ * N + colBase + bR;
    }

    float acc[8][8];
    #pragma unroll
    for (int i = 0; i < 8; i++)
        #pragma unroll
        for (int j = 0; j < 8; j++) acc[i][j] = 0.f;

    for (int kt = 0; kt < K; kt += BK) {
        float4 a4 = *reinterpret_cast<const float4*>(Ap);
        Ap += BK;
        float4 b4 = *reinterpret_cast<const float4*>(Bp);
        if (BT) Bp += BK; else Bp += (long long)BK * N;

        As[aK + 0][aRow] = a4.x;
        As[aK + 1][aRow] = a4.y;
        As[aK + 2][aRow] = a4.z;
        As[aK + 3][aRow] = a4.w;
        if (BT) {
            Bs[bK_ + 0][bR] = b4.x;
            Bs[bK_ + 1][bR] = b4.y;
            Bs[bK_ + 2][bR] = b4.z;
            Bs[bK_ + 3][bR] = b4.w;
        } else {
            *reinterpret_cast<float4*>(&Bs[bK_][bR]) = b4;
        }
        __syncthreads();

        #pragma unroll
        for (int kk = 0; kk < BK; kk++) {
            float ar[8], br[8];
            *reinterpret_cast<float4*>(ar)     = *reinterpret_cast<const float4*>(&As[kk][ty * 8]);
            *reinterpret_cast<float4*>(ar + 4) = *reinterpret_cast<const float4*>(&As[kk][ty * 8 + 4]);
            *reinterpret_cast<float4*>(br)     = *reinterpret_cast<const float4*>(&Bs[kk][tx * 8]);
            *reinterpret_cast<float4*>(br + 4) = *reinterpret_cast<const float4*>(&Bs[kk][tx * 8 + 4]);
            #pragma unroll
            for (int i = 0; i < 8; i++)
                #pragma unroll
                for (int j = 0; j < 8; j++)
                    acc[i][j] = fmaf(ar[i], br[j], acc[i][j]);
        }
        __syncthreads();
    }

    float bv[8];
    #pragma unroll
    for (int j = 0; j < 8; j++)
        bv[j] = bias ? bias[colBase + tx * 8 + j] : 0.f;

    #pragma unroll
    for (int i = 0; i < 8; i++) {
        float4 o0, o1;
        o0.x = alpha * acc[i][0] + bv[0];
        o0.y = alpha * acc[i][1] + bv[1];
        o0.z = alpha * acc[i][2] + bv[2];
        o0.w = alpha * acc[i][3] + bv[3];
        o1.x = alpha * acc[i][4] + bv[4];
        o1.y = alpha * acc[i][5] + bv[5];
        o1.z = alpha * acc[i][6] + bv[6];
        o1.w = alpha * acc[i][7] + bv[7];
        long long off = (long long)(rowBase + ty * 8 + i) * N + colBase + tx * 8;
        *reinterpret_cast<float4*>(&C[off])     = o0;
        *reinterpret_cast<float4*>(&C[off + 4]) = o1;
    }
}

// ---------------------------------------------------------------------------
// Row softmax, in place. One 256-thread CTA per row of length ncols.
// ---------------------------------------------------------------------------
__global__ void softmax_k(float* __restrict__ S, int ncols)
{
    float* row = S + (long long)blockIdx.x * ncols;
    const int tid = threadIdx.x;
    __shared__ float red[8];

    float m = -3.4e38f;
    for (int c = tid; c < ncols; c += 256) m = fmaxf(m, row[c]);
    #pragma unroll
    for (int o = 16; o; o >>= 1) m = fmaxf(m, __shfl_xor_sync(0xffffffffu, m, o));
    if ((tid & 31) == 0) red[tid >> 5] = m;
    __syncthreads();
    m = red[0];
    #pragma unroll
    for (int w = 1; w < 8; w++) m = fmaxf(m, red[w]);

    float sum = 0.f;
    for (int c = tid; c < ncols; c += 256) {
        float e = __expf(row[c] - m);
        row[c] = e;
        sum += e;
    }
    #pragma unroll
    for (int o = 16; o; o >>= 1) sum += __shfl_xor_sync(0xffffffffu, sum, o);
    __syncthreads();            // red reuse
    if ((tid & 31) == 0) red[tid >> 5] = sum;
    __syncthreads();
    sum = 0.f;
    #pragma unroll
    for (int w = 0; w < 8; w++) sum += red[w];

    const float inv = 1.f / sum;
    for (int c = tid; c < ncols; c += 256) row[c] *= inv;
}

// ---------------------------------------------------------------------------
// out = h + sigmoid(gpre) * ctx   (vectorized float4, exact coverage)
// ---------------------------------------------------------------------------
__global__ void finalize_k(const float4* __restrict__ h, const float4* __restrict__ gpre,
                           const float4* __restrict__ ctx, float4* __restrict__ out)
{
    const int i = blockIdx.x * blockDim.x + threadIdx.x;
    float4 hv = h[i], gv = gpre[i], cv = ctx[i];
    float4 o;
    o.x = hv.x + cv.x / (1.f + __expf(-gv.x));
    o.y = hv.y + cv.y / (1.f + __expf(-gv.y));
    o.z = hv.z + cv.z / (1.f + __expf(-gv.z));
    o.w = hv.w + cv.w / (1.f + __expf(-gv.w));
    out[i] = o;
}

// ---------------------------------------------------------------------------
// kernel_launch
// Input order: h_s, h_c, then (W,b) for qs, kc, vc, qc, ks, vs, gs, gc.
// Output: concat(h_s_updated, h_c_updated), 2*B*L*D floats.
// ---------------------------------------------------------------------------
extern "C" void kernel_launch(void* const* d_in, const int* in_sizes, int n_in,
                              void* d_out, int out_size)
{
    const float* h_s = (const float*)d_in[0];
    const float* h_c = (const float*)d_in[1];
    const float *Wqs = (const float*)d_in[2],  *bqs = (const float*)d_in[3];
    const float *Wkc = (const float*)d_in[4],  *bkc = (const float*)d_in[5];
    const float *Wvc = (const float*)d_in[6],  *bvc = (const float*)d_in[7];
    const float *Wqc = (const float*)d_in[8],  *bqc = (const float*)d_in[9];
    const float *Wks = (const float*)d_in[10], *bks = (const float*)d_in[11];
    const float *Wvs = (const float*)d_in[12], *bvs = (const float*)d_in[13];
    const float *Wgs = (const float*)d_in[14], *bgs = (const float*)d_in[15];
    const float *Wgc = (const float*)d_in[16], *bgc = (const float*)d_in[17];
    float* out = (float*)d_out;

    float *q, *k, *v, *g, *s;
    cudaGetSymbolAddress((void**)&q, g_q);
    cudaGetSymbolAddress((void**)&k, g_k);
    cudaGetSymbolAddress((void**)&v, g_v);
    cudaGetSymbolAddress((void**)&g, g_g);
    cudaGetSymbolAddress((void**)&s, g_s);

    const dim3 blk(256);
    const int M = NB * NL;                 // 16384

    // Phase 1: projections (NT GEMM, bias).  dir0 updates h_s; dir1 updates h_c.
    {
        dim3 gp(ND / 128, M / 128, 1);
        gemm_k<true><<<gp, blk>>>(h_s, Wqs, bqs, q,        M, ND, ND, 1.f, 0, 0, 0);
        gemm_k<true><<<gp, blk>>>(h_c, Wkc, bkc, k,        M, ND, ND, 1.f, 0, 0, 0);
        gemm_k<true><<<gp, blk>>>(h_c, Wvc, bvc, v,        M, ND, ND, 1.f, 0, 0, 0);
        gemm_k<true><<<gp, blk>>>(h_s, Wgs, bgs, g,        M, ND, ND, 1.f, 0, 0, 0);
        gemm_k<true><<<gp, blk>>>(h_c, Wqc, bqc, q + BLD,  M, ND, ND, 1.f, 0, 0, 0);
        gemm_k<true><<<gp, blk>>>(h_s, Wks, bks, k + BLD,  M, ND, ND, 1.f, 0, 0, 0);
        gemm_k<true><<<gp, blk>>>(h_s, Wvs, bvs, v + BLD,  M, ND, ND, 1.f, 0, 0, 0);
        gemm_k<true><<<gp, blk>>>(h_c, Wgc, bgc, g + BLD,  M, ND, ND, 1.f, 0, 0, 0);
    }

    // Phase 2a: scores = (1/sqrt(D)) * Q @ K^T, batched over 16 (2 dirs x 8 batches)
    {
        const float alpha = 1.0f / sqrtf((float)ND);
        dim3 gsd(NL / 128, NL / 128, 16);
        gemm_k<true><<<gsd, blk>>>(q, k, nullptr, s, NL, NL, ND, alpha,
                                   (long long)NL * ND, (long long)NL * ND,
                                   (long long)NL * NL);
    }

    // Phase 2b: row softmax (32768 rows of 2048)
    softmax_k<<<16 * NL, 256>>>(s, NL);

    // Phase 2c: context = P @ V (NN GEMM), write over Q buffer (dead after 2a)
    {
        dim3 gc(ND / 128, NL / 128, 16);
        gemm_k<false><<<gc, blk>>>(s, v, nullptr, q, NL, ND, NL, 1.f,
                                   (long long)NL * NL, (long long)NL * ND,
                                   (long long)NL * ND);
    }

    // Phase 3: out = h + sigmoid(g) * ctx
    {
        const int n4 = BLD / 4;               // 2,097,152
        finalize_k<<<n4 / 256, 256>>>((const float4*)h_s, (const float4*)g,
                                      (const float4*)q, (float4*)out);
        finalize_k<<<n4 / 256, 256>>>((const float4*)h_c, (const float4*)(g + BLD),
                                      (const float4*)(q + BLD), (float4*)(out + BLD));
    }
}

// round 2
// speedup vs baseline: 1.0014x; 1.0014x over previous
#include <cuda_runtime.h>
#include <math.h>

// Problem constants
#define NB 8
#define NL 2048
#define ND 512
#define BLD (NB*NL*ND)      // 8,388,608 elems per tensor
#define BLL_ ((long long)NB*NL*NL)  // 33,554,432 per direction score matrix

// Scratch (device globals: allocation-free per harness rules)
__device__ float g_q[2ULL*BLD];   // Q per direction; reused as context output after PV
__device__ float g_k[2ULL*BLD];
__device__ float g_v[2ULL*BLD];
__device__ float g_g[2ULL*BLD];   // gate pre-activations
__device__ float g_s[2ULL*BLL_];  // scores / probs

// ---------------------------------------------------------------------------
// Generic tiled FP32 GEMM.
//   BT = true : C[m,n] = alpha * sum_k A[m,k] * B[n,k]  (+bias[n])   "NT"
//   BT = false: C[m,n] = alpha * sum_k A[m,k] * B[k,n]  (+bias[n])   "NN"
// Tiles: 128x128x8, 256 threads, 8x8 per-thread microtile.
// Requires M%128==0, N%128==0, K%8==0 (all shapes here satisfy this).
// Batched via blockIdx.z with element strides sA/sB/sC.
// ---------------------------------------------------------------------------
template<bool BT>
__global__ __launch_bounds__(256, 2)
void gemm_k(const float* __restrict__ A, const float* __restrict__ Bm,
            const float* __restrict__ bias, float* __restrict__ C,
            int M, int N, int K, float alpha,
            long long sA, long long sB, long long sC)
{
    constexpr int BM = 128, BN = 128, BK = 8;
    __shared__ float As[BK][BM];
    __shared__ float Bs[BK][BN];

    A  += (long long)blockIdx.z * sA;
    Bm += (long long)blockIdx.z * sB;
    C  += (long long)blockIdx.z * sC;

    const int tid = threadIdx.x;
    const int tx = tid & 15;        // 0..15 -> N microtiles
    const int ty = tid >> 4;        // 0..15 -> M microtiles
    const int rowBase = blockIdx.y * BM;
    const int colBase = blockIdx.x * BN;

    // A global-load mapping: 128 rows x 8 k, float4 per thread (2 threads/row)
    const int aRow = tid >> 1;
    const int aK   = (tid & 1) * 4;
    const float* Ap = A + (long long)(rowBase + aRow) * K + aK;

    // B global-load mapping
    int bR, bK_;
    const float* Bp;
    if (BT) {  // B is (N,K) row-major: same pattern as A over N rows
        bR  = tid >> 1;
        bK_ = (tid & 1) * 4;
        Bp  = Bm + (long long)(colBase + bR) * K + bK_;
    } else {   // B is (K,N) row-major: 8 k-rows x 32 threads x float4
        bK_ = tid >> 5;           // 0..7
        bR  = (tid & 31) * 4;     // 0..124
        Bp  = Bm + (long long)bK_ * N + colBase + bR;
    }

    float acc[8][8];
    #pragma unroll
    for (int i = 0; i < 8; i++)
        #pragma unroll
        for (int j = 0; j < 8; j++) acc[i][j] = 0.f;

    for (int kt = 0; kt < K; kt += BK) {
        float4 a4 = *reinterpret_cast<const float4*>(Ap);
        Ap += BK;
        float4 b4 = *reinterpret_cast<const float4*>(Bp);
        if (BT) Bp += BK; else Bp += (long long)BK * N;

        As[aK + 0][aRow] = a4.x;
        As[aK + 1][aRow] = a4.y;
        As[aK + 2][aRow] = a4.z;
        As[aK + 3][aRow] = a4.w;
        if (BT) {
            Bs[bK_ + 0][bR] = b4.x;
            Bs[bK_ + 1][bR] = b4.y;
            Bs[bK_ + 2][bR] = b4.z;
            Bs[bK_ + 3][bR] = b4.w;
        } else {
            *reinterpret_cast<float4*>(&Bs[bK_][bR]) = b4;
        }
        __syncthreads();

        #pragma unroll
        for (int kk = 0; kk < BK; kk++) {
            float ar[8], br[8];
            *reinterpret_cast<float4*>(ar)     = *reinterpret_cast<const float4*>(&As[kk][ty * 8]);
            *reinterpret_cast<float4*>(ar + 4) = *reinterpret_cast<const float4*>(&As[kk][ty * 8 + 4]);
            *reinterpret_cast<float4*>(br)     = *reinterpret_cast<const float4*>(&Bs[kk][tx * 8]);
            *reinterpret_cast<float4*>(br + 4) = *reinterpret_cast<const float4*>(&Bs[kk][tx * 8 + 4]);
            #pragma unroll
            for (int i = 0; i < 8; i++)
                #pragma unroll
                for (int j = 0; j < 8; j++)
                    acc[i][j] = fmaf(ar[i], br[j], acc[i][j]);
        }
        __syncthreads();
    }

    float bv[8];
    #pragma unroll
    for (int j = 0; j < 8; j++)
        bv[j] = bias ? bias[colBase + tx * 8 + j] : 0.f;

    #pragma unroll
    for (int i = 0; i < 8; i++) {
        float4 o0, o1;
        o0.x = alpha * acc[i][0] + bv[0];
        o0.y = alpha * acc[i][1] + bv[1];
        o0.z = alpha * acc[i][2] + bv[2];
        o0.w = alpha * acc[i][3] + bv[3];
        o1.x = alpha * acc[i][4] + bv[4];
        o1.y = alpha * acc[i][5] + bv[5];
        o1.z = alpha * acc[i][6] + bv[6];
        o1.w = alpha * acc[i][7] + bv[7];
        long long off = (long long)(rowBase + ty * 8 + i) * N + colBase + tx * 8;
        *reinterpret_cast<float4*>(&C[off])     = o0;
        *reinterpret_cast<float4*>(&C[off + 4]) = o1;
    }
}

// ---------------------------------------------------------------------------
// Row softmax, in place. One 256-thread CTA per row of length ncols.
// ---------------------------------------------------------------------------
__global__ void softmax_k(float* __restrict__ S, int ncols)
{
    float* row = S + (long long)blockIdx.x * ncols;
    const int tid = threadIdx.x;
    __shared__ float red[8];

    float m = -3.4e38f;
    for (int c = tid; c < ncols; c += 256) m = fmaxf(m, row[c]);
    #pragma unroll
    for (int o = 16; o; o >>= 1) m = fmaxf(m, __shfl_xor_sync(0xffffffffu, m, o));
    if ((tid & 31) == 0) red[tid >> 5] = m;
    __syncthreads();
    m = red[0];
    #pragma unroll
    for (int w = 1; w < 8; w++) m = fmaxf(m, red[w]);

    float sum = 0.f;
    for (int c = tid; c < ncols; c += 256) {
        float e = __expf(row[c] - m);
        row[c] = e;
        sum += e;
    }
    #pragma unroll
    for (int o = 16; o; o >>= 1) sum += __shfl_xor_sync(0xffffffffu, sum, o);
    __syncthreads();            // red reuse
    if ((tid & 31) == 0) red[tid >> 5] = sum;
    __syncthreads();
    sum = 0.f;
    #pragma unroll
    for (int w = 0; w < 8; w++) sum += red[w];

    const float inv = 1.f / sum;
    for (int c = tid; c < ncols; c += 256) row[c] *= inv;
}

// ---------------------------------------------------------------------------
// out = h + sigmoid(gpre) * ctx   (vectorized float4, exact coverage)
// ---------------------------------------------------------------------------
__global__ void finalize_k(const float4* __restrict__ h, const float4* __restrict__ gpre,
                           const float4* __restrict__ ctx, float4* __restrict__ out)
{
    const int i = blockIdx.x * blockDim.x + threadIdx.x;
    float4 hv = h[i], gv = gpre[i], cv = ctx[i];
    float4 o;
    o.x = hv.x + cv.x / (1.f + __expf(-gv.x));
    o.y = hv.y + cv.y / (1.f + __expf(-gv.y));
    o.z = hv.z + cv.z / (1.f + __expf(-gv.z));
    o.w = hv.w + cv.w / (1.f + __expf(-gv.w));
    out[i] = o;
}

// ---------------------------------------------------------------------------
// kernel_launch
// Input order: h_s, h_c, then (W,b) for qs, kc, vc, qc, ks, vs, gs, gc.
// Output: concat(h_s_updated, h_c_updated), 2*B*L*D floats.
// ---------------------------------------------------------------------------
extern "C" void kernel_launch(void* const* d_in, const int* in_sizes, int n_in,
                              void* d_out, int out_size)
{
    const float* h_s = (const float*)d_in[0];
    const float* h_c = (const float*)d_in[1];
    const float *Wqs = (const float*)d_in[2],  *bqs = (const float*)d_in[3];
    const float *Wkc = (const float*)d_in[4],  *bkc = (const float*)d_in[5];
    const float *Wvc = (const float*)d_in[6],  *bvc = (const float*)d_in[7];
    const float *Wqc = (const float*)d_in[8],  *bqc = (const float*)d_in[9];
    const float *Wks = (const float*)d_in[10], *bks = (const float*)d_in[11];
    const float *Wvs = (const float*)d_in[12], *bvs = (const float*)d_in[13];
    const float *Wgs = (const float*)d_in[14], *bgs = (const float*)d_in[15];
    const float *Wgc = (const float*)d_in[16], *bgc = (const float*)d_in[17];
    float* out = (float*)d_out;

    float *q, *k, *v, *g, *s;
    cudaGetSymbolAddress((void**)&q, g_q);
    cudaGetSymbolAddress((void**)&k, g_k);
    cudaGetSymbolAddress((void**)&v, g_v);
    cudaGetSymbolAddress((void**)&g, g_g);
    cudaGetSymbolAddress((void**)&s, g_s);

    const dim3 blk(256);
    const int M = NB * NL;                 // 16384

    // Phase 1: projections (NT GEMM, bias).  dir0 updates h_s; dir1 updates h_c.
    {
        dim3 gp(ND / 128, M / 128, 1);
        gemm_k<true><<<gp, blk>>>(h_s, Wqs, bqs, q,        M, ND, ND, 1.f, 0, 0, 0);
        gemm_k<true><<<gp, blk>>>(h_c, Wkc, bkc, k,        M, ND, ND, 1.f, 0, 0, 0);
        gemm_k<true><<<gp, blk>>>(h_c, Wvc, bvc, v,        M, ND, ND, 1.f, 0, 0, 0);
        gemm_k<true><<<gp, blk>>>(h_s, Wgs, bgs, g,        M, ND, ND, 1.f, 0, 0, 0);
        gemm_k<true><<<gp, blk>>>(h_c, Wqc, bqc, q + BLD,  M, ND, ND, 1.f, 0, 0, 0);
        gemm_k<true><<<gp, blk>>>(h_s, Wks, bks, k + BLD,  M, ND, ND, 1.f, 0, 0, 0);
        gemm_k<true><<<gp, blk>>>(h_s, Wvs, bvs, v + BLD,  M, ND, ND, 1.f, 0, 0, 0);
        gemm_k<true><<<gp, blk>>>(h_c, Wgc, bgc, g + BLD,  M, ND, ND, 1.f, 0, 0, 0);
    }

    // Phase 2a: scores = (1/sqrt(D)) * Q @ K^T, batched over 16 (2 dirs x 8 batches)
    {
        const float alpha = 1.0f / sqrtf((float)ND);
        dim3 gsd(NL / 128, NL / 128, 16);
        gemm_k<true><<<gsd, blk>>>(q, k, nullptr, s, NL, NL, ND, alpha,
                                   (long long)NL * ND, (long long)NL * ND,
                                   (long long)NL * NL);
    }

    // Phase 2b: row softmax (32768 rows of 2048)
    softmax_k<<<16 * NL, 256>>>(s, NL);

    // Phase 2c: context = P @ V (NN GEMM), write over Q buffer (dead after 2a)
    {
        dim3 gc(ND / 128, NL / 128, 16);
        gemm_k<false><<<gc, blk>>>(s, v, nullptr, q, NL, ND, NL, 1.f,
                                   (long long)NL * NL, (long long)NL * ND,
                                   (long long)NL * ND);
    }

    // Phase 3: out = h + sigmoid(g) * ctx
    {
        const int n4 = BLD / 4;               // 2,097,152
        finalize_k<<<n4 / 256, 256>>>((const float4*)h_s, (const float4*)g,
                                      (const float4*)q, (float4*)out);
        finalize_k<<<n4 / 256, 256>>>((const float4*)h_c, (const float4*)(g + BLD),
                                      (const float4*)(q + BLD), (float4*)(out + BLD));
    }
}